// round 14
// baseline (speedup 1.0000x reference)
#include <cuda_runtime.h>
#include <cstddef>

#define WORDS   1000000
#define EMB_D   64
#define KTH     4
#define BATCH   8192

#define E_ELEMS   ((long)WORDS * EMB_D)          // 64,000,000
#define B_ELEMS   ((long)WORDS * KTH)            // 4,000,000
#define TOT_ELEMS (E_ELEMS + B_ELEMS)            // 68,000,000
#define K_CH      (TOT_ELEMS / 4)                // 17,000,000 float4 chunks
#define E_CH      (E_ELEMS / 4)                  // 16,000,000
#define RB        128                            // reduce blocks
#define INVB      (1.0f / (float)BATCH)

#define TPB     256
#define UNROLL  4
#define CPB     (TPB * UNROLL)                   // 1024 chunks per block

// Per-block partials (fully overwritten each launch -> graph-replay safe).
__device__ float g_pw[RB][EMB_D];
__device__ float g_pb[RB][KTH];
__device__ int   g_pc[RB];
// Reduce-completion ticket (only RB blocks touch it; last one resets -> replay safe).
__device__ unsigned int g_ticket;

// ---------------------------------------------------------------------------
// Helpers
// ---------------------------------------------------------------------------
__device__ __forceinline__ float load_src(long s,
                                          const float* __restrict__ emb,
                                          const float* __restrict__ bia) {
    return (s < E_ELEMS) ? __ldg(emb + s) : __ldg(bia + (s - E_ELEMS));
}

__device__ __forceinline__ float4 load_chunk_cs(long k,
                                                const float* __restrict__ emb,
                                                const float* __restrict__ bia) {
    const float4* p = (k < E_CH)
        ? (reinterpret_cast<const float4*>(emb) + k)
        : (reinterpret_cast<const float4*>(bia) + (k - E_CH));
    return __ldcs(p);
}

// ---------------------------------------------------------------------------
// Reduce body (blocks 0..RB-1)
// ---------------------------------------------------------------------------
__device__ void reduce_body(const float* __restrict__ embed,
                            const float* __restrict__ bias,
                            const int*   __restrict__ ctx_id,
                            const int*   __restrict__ tgt,
                            const int*   __restrict__ lab) {
    __shared__ float s_ctx[EMB_D];
    __shared__ float s_bias[KTH];
    __shared__ float s_w[8][EMB_D];
    __shared__ float s_b[8][KTH];
    __shared__ int   s_c[8];

    const int tid = threadIdx.x;
    const int ctx = __ldg(ctx_id);
    if (tid < EMB_D) s_ctx[tid]  = __ldg(embed + (size_t)ctx * EMB_D + tid);
    if (tid < KTH)   s_bias[tid] = __ldg(bias  + (size_t)ctx * KTH + tid);
    __syncthreads();

    const int warp  = tid >> 5;
    const int lane  = tid & 31;
    const int gwarp = blockIdx.x * 8 + warp;     // 1024 warps total
    const int twarps = RB * 8;

    const float2 c2 = reinterpret_cast<const float2*>(s_ctx)[lane];

    float wx = 0.0f, wy = 0.0f;
    float b0 = 0.0f, b1 = 0.0f, b2 = 0.0f, b3 = 0.0f;
    int corr = 0;

    for (int b = gwarp; b < BATCH; b += twarps) {
        const int t = __ldg(tgt + b);
        const float2 e2 =
            reinterpret_cast<const float2*>(embed + (size_t)t * EMB_D)[lane];
        float p = e2.x * c2.x + e2.y * c2.y;
        #pragma unroll
        for (int o = 16; o; o >>= 1) p += __shfl_xor_sync(0xffffffffu, p, o);
        const float dot = p;

        const int   L    = __ldg(lab + b);
        const float labf = (float)L;

        float taurow = 0.0f;
        int   plabel = KTH + 1;
        float tj[KTH];
        #pragma unroll
        for (int j = KTH - 1; j >= 0; j--) {
            const float db = dot - s_bias[j];
            if (db <= 0.0f) plabel = j + 1;
            const float yt  = (j < L) ? 1.0f : -1.0f;
            const float tau = (db * yt > 0.0f) ? 0.0f : labf;
            tj[j] = tau;
            taurow += tau;
        }
        if (lane == 0) {
            b0 += tj[0]; b1 += tj[1]; b2 += tj[2]; b3 += tj[3];
            if (plabel == L) corr++;
        }
        wx += taurow * e2.x;
        wy += taurow * e2.y;
    }

    s_w[warp][2 * lane]     = wx;
    s_w[warp][2 * lane + 1] = wy;
    if (lane == 0) {
        s_b[warp][0] = b0; s_b[warp][1] = b1; s_b[warp][2] = b2; s_b[warp][3] = b3;
        s_c[warp] = corr;
    }
    __syncthreads();

    if (tid < EMB_D) {
        float s = 0.0f;
        #pragma unroll
        for (int w = 0; w < 8; w++) s += s_w[w][tid];
        g_pw[blockIdx.x][tid] = s;
    }
    if (tid < KTH) {
        float s = 0.0f;
        #pragma unroll
        for (int w = 0; w < 8; w++) s += s_b[w][tid];
        g_pb[blockIdx.x][tid] = s;
    }
    if (tid == 0) {
        int s = 0;
        #pragma unroll
        for (int w = 0; w < 8; w++) s += s_c[w];
        g_pc[blockIdx.x] = s;
    }
}

// ---------------------------------------------------------------------------
// Patch body (run by LAST reduce block, concurrent with copy; writes only the
// patched elements + acc + head + tail, all disjoint from copy stores).
// ---------------------------------------------------------------------------
__device__ void patch_body(const float* __restrict__ emb,
                           const float* __restrict__ bia,
                           const int*   __restrict__ ctx_id,
                           float* __restrict__ out) {
    __shared__ float t_w[4][EMB_D];
    __shared__ float s_w[EMB_D];
    __shared__ float s_pb[4][KTH];
    __shared__ int   s_pc[4];
    __shared__ float s_b[KTH];
    __shared__ int   s_c;

    const int tid  = threadIdx.x;
    const int lane = tid & 31;
    const int warp = tid >> 5;

    // g_pw: 128x64. Group g = tid>>6 accumulates rows g, g+4, ... (coalesced).
    {
        const int g = tid >> 6;
        const int c = tid & 63;
        float acc = 0.0f;
        #pragma unroll
        for (int i = 0; i < RB / 4; i++)
            acc += g_pw[g + 4 * i][c];
        t_w[g][c] = acc;
    }

    // g_pb rows as float4 + shuffle reduce; g_pc alongside.
    if (tid < 128) {
        float4 v = reinterpret_cast<const float4*>(g_pb)[tid];
        int c = g_pc[tid];
        #pragma unroll
        for (int o = 16; o; o >>= 1) {
            v.x += __shfl_xor_sync(0xffffffffu, v.x, o);
            v.y += __shfl_xor_sync(0xffffffffu, v.y, o);
            v.z += __shfl_xor_sync(0xffffffffu, v.z, o);
            v.w += __shfl_xor_sync(0xffffffffu, v.w, o);
            c   += __shfl_xor_sync(0xffffffffu, c, o);
        }
        if (lane == 0) {
            s_pb[warp][0] = v.x; s_pb[warp][1] = v.y;
            s_pb[warp][2] = v.z; s_pb[warp][3] = v.w;
            s_pc[warp] = c;
        }
    }
    __syncthreads();

    if (tid < EMB_D)
        s_w[tid] = t_w[0][tid] + t_w[1][tid] + t_w[2][tid] + t_w[3][tid];
    if (tid >= 64 && tid < 64 + KTH) {
        const int j = tid - 64;
        s_b[j] = s_pb[0][j] + s_pb[1][j] + s_pb[2][j] + s_pb[3][j];
    }
    if (tid == 128)
        s_c = s_pc[0] + s_pc[1] + s_pc[2] + s_pc[3];
    __syncthreads();

    const int  ctx   = __ldg(ctx_id);
    const long wbase = (long)ctx * EMB_D;
    const long bbase = E_ELEMS + (long)ctx * KTH;

    if (tid == 128) out[0] = (float)s_c * INVB;

    // Context embed row (covers head out[1..3] if ctx == 0).
    if (tid < EMB_D)
        out[1 + wbase + tid] = __ldg(emb + wbase + tid) + s_w[tid] * INVB;

    // Context bias row (covers tail out[TOT] if ctx == WORDS-1).
    if (tid >= 64 && tid < 64 + KTH) {
        const int j = tid - 64;
        out[1 + bbase + j] = __ldg(bia + (long)ctx * KTH + j) - s_b[j] * INVB;
    }

    // Head out[1..3]: copy never writes chunk 0.
    if (tid >= 129 && tid < 132 && ctx != 0) {
        const int j = tid - 129;
        out[1 + j] = __ldg(emb + j);
    }
    // Tail out[TOT].
    if (tid == 132 && ctx != WORDS - 1)
        out[TOT_ELEMS] = __ldg(bia + B_ELEMS - 1);
}

// ---------------------------------------------------------------------------
// Single fused kernel.
//   blocks < RB: reduce -> fence -> ticket; last reduce block patches.
//   all blocks:  shifted streaming copy. The overlap-with-patched-range test
//                is hoisted to ONE block-uniform branch; only the <=2 blocks
//                that overlap take the element-wise path.
// ---------------------------------------------------------------------------
__global__ void __launch_bounds__(TPB)
prank_main_kernel(const float* __restrict__ emb,
                  const float* __restrict__ bia,
                  const int*   __restrict__ ctx_id,
                  const int*   __restrict__ tgt,
                  const int*   __restrict__ lab,
                  float* __restrict__ out) {
    if (blockIdx.x < RB) {
        reduce_body(emb, bia, ctx_id, tgt, lab);

        __shared__ unsigned int s_last;
        __threadfence();                 // publish this block's partials (RB blocks only)
        __syncthreads();
        if (threadIdx.x == 0) {
            const unsigned int old = atomicAdd(&g_ticket, 1u);
            s_last = (old == RB - 1u) ? 1u : 0u;
            if (s_last) g_ticket = 0;    // reset -> graph-replay safe
        }
        __syncthreads();
        if (s_last) {
            __threadfence();             // acquire other reduce blocks' partials
            patch_body(emb, bia, ctx_id, out);
        }
    }

    const long base = (long)blockIdx.x * CPB + 1;
    const int  tid  = threadIdx.x;
    const int  lane = tid & 31;

    long   k[UNROLL];
    float4 B[UNROLL];
    float  prev[UNROLL];

    #pragma unroll
    for (int i = 0; i < UNROLL; i++) {
        long kk = base + (long)i * TPB + tid;
        if (kk >= K_CH) kk = K_CH - 1;            // clamp keeps warp converged
        k[i] = kk;
        B[i] = load_chunk_cs(kk, emb, bia);
    }

    #pragma unroll
    for (int i = 0; i < UNROLL; i++) {
        prev[i] = __shfl_up_sync(0xffffffffu, B[i].w, 1);
        if (lane == 0) prev[i] = load_src(4 * k[i] - 1, emb, bia);
    }

    // Block-uniform overlap test against the patched output ranges.
    const int  ctx    = __ldg(ctx_id);
    const long wlo    = 1 + (long)ctx * EMB_D;          // [wlo, wlo+EMB_D)
    const long blo    = 1 + E_ELEMS + (long)ctx * KTH;  // [blo, blo+KTH)
    const long blk_lo = 4 * base;                        // block writes [blk_lo, blk_hi)
    const long blk_hi = 4 * (base + CPB);
    const bool ov_blk = (blk_lo < wlo + EMB_D && blk_hi > wlo) ||
                        (blk_lo < blo + KTH   && blk_hi > blo);

    if (!ov_blk) {
        // Fast path: pure streaming stores, no per-chunk range logic.
        #pragma unroll
        for (int i = 0; i < UNROLL; i++) {
            const long kk = base + (long)i * TPB + tid;
            if (kk < K_CH) {
                __stcs(reinterpret_cast<float4*>(out) + kk,
                       make_float4(prev[i], B[i].x, B[i].y, B[i].z));
            }
        }
    } else {
        // Slow path (<=2 blocks chip-wide): skip patched slots element-wise.
        const long whi = wlo + EMB_D;
        const long bhi = blo + KTH;
        #pragma unroll
        for (int i = 0; i < UNROLL; i++) {
            const long kk = base + (long)i * TPB + tid;
            if (kk < K_CH) {
                const long s = 4 * kk;
                float oo[4] = {prev[i], B[i].x, B[i].y, B[i].z};
                #pragma unroll
                for (int c = 0; c < 4; c++) {
                    const long idx = s + c;
                    const bool patched = (idx >= wlo && idx < whi) ||
                                         (idx >= blo && idx < bhi);
                    if (!patched) out[idx] = oo[c];
                }
            }
        }
    }
}

extern "C" void kernel_launch(void* const* d_in, const int* in_sizes, int n_in,
                              void* d_out, int out_size) {
    const float* in_embed = (const float*)d_in[0];
    const float* in_bias  = (const float*)d_in[1];
    const int*   ctx_id   = (const int*)d_in[2];
    const int*   tgt      = (const int*)d_in[3];
    const int*   lab      = (const int*)d_in[4];
    float* out = (float*)d_out;
    (void)n_in; (void)out_size; (void)in_sizes;

    const long nchunks = K_CH - 1;                       // chunks 1..K_CH-1
    const int  blocks  = (int)((nchunks + CPB - 1) / CPB);
    prank_main_kernel<<<blocks, TPB>>>(in_embed, in_bias, ctx_id, tgt, lab, out);
}

// round 15
// speedup vs baseline: 1.0694x; 1.0694x over previous
#include <cuda_runtime.h>
#include <cstddef>

#define WORDS   1000000
#define EMB_D   64
#define KTH     4
#define BATCH   8192

#define E_ELEMS   ((long)WORDS * EMB_D)          // 64,000,000
#define B_ELEMS   ((long)WORDS * KTH)            // 4,000,000
#define TOT_ELEMS (E_ELEMS + B_ELEMS)            // 68,000,000
#define K_CH      (TOT_ELEMS / 4)                // 17,000,000 float4 chunks
#define E_CH      (E_ELEMS / 4)                  // 16,000,000
#define RB        128                            // reduce blocks
#define INVB      (1.0f / (float)BATCH)

#define TPB     256
#define UNROLL  4
#define CPB     (TPB * UNROLL)                   // 1024 chunks per block

// Per-block partials (fully overwritten each launch -> graph-replay safe).
__device__ float g_pw[RB][EMB_D];
__device__ float g_pb[RB][KTH];
__device__ int   g_pc[RB];
// Sync state: ticket counted by reduce blocks (last resets), flag set by last
// reduce block (reset by last consumer ack), ack counted by consumers (last
// resets). Everything returns to 0 each launch -> graph-replay safe.
__device__ unsigned int g_ticket;
__device__ unsigned int g_flag;
__device__ unsigned int g_ack;

// ---------------------------------------------------------------------------
// Helpers
// ---------------------------------------------------------------------------
__device__ __forceinline__ float load_src(long s,
                                          const float* __restrict__ emb,
                                          const float* __restrict__ bia) {
    return (s < E_ELEMS) ? __ldg(emb + s) : __ldg(bia + (s - E_ELEMS));
}

__device__ __forceinline__ float4 load_chunk_cs(long k,
                                                const float* __restrict__ emb,
                                                const float* __restrict__ bia) {
    const float4* p = (k < E_CH)
        ? (reinterpret_cast<const float4*>(emb) + k)
        : (reinterpret_cast<const float4*>(bia) + (k - E_CH));
    return __ldcs(p);
}

// ---------------------------------------------------------------------------
// Reduce body (blocks 0..RB-1)
// ---------------------------------------------------------------------------
__device__ void reduce_body(const float* __restrict__ embed,
                            const float* __restrict__ bias,
                            const int*   __restrict__ ctx_id,
                            const int*   __restrict__ tgt,
                            const int*   __restrict__ lab) {
    __shared__ float s_ctx[EMB_D];
    __shared__ float s_bias[KTH];
    __shared__ float s_w[8][EMB_D];
    __shared__ float s_b[8][KTH];
    __shared__ int   s_c[8];

    const int tid = threadIdx.x;
    const int ctx = __ldg(ctx_id);
    if (tid < EMB_D) s_ctx[tid]  = __ldg(embed + (size_t)ctx * EMB_D + tid);
    if (tid < KTH)   s_bias[tid] = __ldg(bias  + (size_t)ctx * KTH + tid);
    __syncthreads();

    const int warp  = tid >> 5;
    const int lane  = tid & 31;
    const int gwarp = blockIdx.x * 8 + warp;     // 1024 warps total
    const int twarps = RB * 8;

    const float2 c2 = reinterpret_cast<const float2*>(s_ctx)[lane];

    float wx = 0.0f, wy = 0.0f;
    float b0 = 0.0f, b1 = 0.0f, b2 = 0.0f, b3 = 0.0f;
    int corr = 0;

    for (int b = gwarp; b < BATCH; b += twarps) {
        const int t = __ldg(tgt + b);
        const float2 e2 =
            reinterpret_cast<const float2*>(embed + (size_t)t * EMB_D)[lane];
        float p = e2.x * c2.x + e2.y * c2.y;
        #pragma unroll
        for (int o = 16; o; o >>= 1) p += __shfl_xor_sync(0xffffffffu, p, o);
        const float dot = p;

        const int   L    = __ldg(lab + b);
        const float labf = (float)L;

        float taurow = 0.0f;
        int   plabel = KTH + 1;
        float tj[KTH];
        #pragma unroll
        for (int j = KTH - 1; j >= 0; j--) {
            const float db = dot - s_bias[j];
            if (db <= 0.0f) plabel = j + 1;
            const float yt  = (j < L) ? 1.0f : -1.0f;
            const float tau = (db * yt > 0.0f) ? 0.0f : labf;
            tj[j] = tau;
            taurow += tau;
        }
        if (lane == 0) {
            b0 += tj[0]; b1 += tj[1]; b2 += tj[2]; b3 += tj[3];
            if (plabel == L) corr++;
        }
        wx += taurow * e2.x;
        wy += taurow * e2.y;
    }

    s_w[warp][2 * lane]     = wx;
    s_w[warp][2 * lane + 1] = wy;
    if (lane == 0) {
        s_b[warp][0] = b0; s_b[warp][1] = b1; s_b[warp][2] = b2; s_b[warp][3] = b3;
        s_c[warp] = corr;
    }
    __syncthreads();

    if (tid < EMB_D) {
        float s = 0.0f;
        #pragma unroll
        for (int w = 0; w < 8; w++) s += s_w[w][tid];
        g_pw[blockIdx.x][tid] = s;
    }
    if (tid < KTH) {
        float s = 0.0f;
        #pragma unroll
        for (int w = 0; w < 8; w++) s += s_b[w][tid];
        g_pb[blockIdx.x][tid] = s;
    }
    if (tid == 0) {
        int s = 0;
        #pragma unroll
        for (int w = 0; w < 8; w++) s += s_c[w];
        g_pc[blockIdx.x] = s;
    }
}

// Merge the context-row correction into one register (consumer blocks only).
__device__ __forceinline__ void merge_elt(float& r, long idx,
                                          long wlo, long whi, long blo, long bhi,
                                          const float* s_w, const float* s_b) {
    if (idx >= wlo && idx < whi) r += s_w[idx - wlo] * INVB;
    if (idx >= blo && idx < bhi) r -= s_b[idx - blo] * INVB;
}

__device__ __forceinline__ long blk_of(long idx) { return (idx - 4) >> 12; }

// ---------------------------------------------------------------------------
// Single fused kernel. All bulk output traffic goes through ONE float4 store
// loop (no scalar bulk stores anywhere -> ptxas cannot degrade it).
// ---------------------------------------------------------------------------
__global__ void __launch_bounds__(TPB)
prank_main_kernel(const float* __restrict__ emb,
                  const float* __restrict__ bia,
                  const int*   __restrict__ ctx_id,
                  const int*   __restrict__ tgt,
                  const int*   __restrict__ lab,
                  float* __restrict__ out) {
    // --- consumer smem (tiny; additive with reduce_body's smem) ---
    __shared__ float c_tw[4][EMB_D];
    __shared__ float c_w[EMB_D];
    __shared__ float c_pb[4][KTH];
    __shared__ int   c_pc[4];
    __shared__ float c_b[KTH];
    __shared__ int   c_c;

    const int tid  = threadIdx.x;
    const int lane = tid & 31;

    if (blockIdx.x < RB) {
        reduce_body(emb, bia, ctx_id, tgt, lab);
        __threadfence();                     // publish partials (RB blocks only)
        __syncthreads();
        if (tid == 0) {
            const unsigned int old = atomicAdd(&g_ticket, 1u);
            if (old == RB - 1u) {
                g_ticket = 0;                // replay-safe reset
                atomicExch(&g_flag, 1u);     // release: all partials published
            }
        }
    }

    const long base = (long)blockIdx.x * CPB + 1;

    // ---- load phase (identical to R8) ----
    long   k[UNROLL];
    float4 B[UNROLL];
    float  prev[UNROLL];

    #pragma unroll
    for (int i = 0; i < UNROLL; i++) {
        long kk = base + (long)i * TPB + tid;
        if (kk >= K_CH) kk = K_CH - 1;       // clamp keeps warp converged
        k[i] = kk;
        B[i] = load_chunk_cs(kk, emb, bia);
    }

    #pragma unroll
    for (int i = 0; i < UNROLL; i++) {
        prev[i] = __shfl_up_sync(0xffffffffu, B[i].w, 1);
        if (lane == 0) prev[i] = load_src(4 * k[i] - 1, emb, bia);
    }

    // ---- consumer branch: <=3 blocks chip-wide merge corrections in-reg ----
    {
        const int  ctx = __ldg(ctx_id);
        const long wlo = 1 + (long)ctx * EMB_D,  whi = wlo + EMB_D;
        const long blo = 1 + E_ELEMS + (long)ctx * KTH,  bhi = blo + KTH;
        const long rlo = 4 * base;
        long rhi = rlo + 4L * CPB;
        if (rhi > 4L * K_CH) rhi = 4L * K_CH;

        const bool w_ov = (rlo < whi && rhi > wlo);
        const bool b_ov = (rlo < bhi && rhi > blo);

        if (w_ov || b_ov) {
            // Wait for all reduce partials (blocks 0..127 are wave-1; safe).
            if (tid == 0) {
                while (atomicAdd(&g_flag, 0u) == 0u) { __nanosleep(64); }
            }
            __syncthreads();
            __threadfence();                 // acquire partials

            // Cooperative reduction of partials into c_w / c_b / c_c.
            {
                const int g = tid >> 6;      // 0..3
                const int c = tid & 63;
                float acc = 0.0f;
                #pragma unroll
                for (int i = 0; i < RB / 4; i++)
                    acc += g_pw[g + 4 * i][c];
                c_tw[g][c] = acc;
            }
            if (tid < 128) {
                float4 v = reinterpret_cast<const float4*>(g_pb)[tid];
                int cc = g_pc[tid];
                #pragma unroll
                for (int o = 16; o; o >>= 1) {
                    v.x += __shfl_xor_sync(0xffffffffu, v.x, o);
                    v.y += __shfl_xor_sync(0xffffffffu, v.y, o);
                    v.z += __shfl_xor_sync(0xffffffffu, v.z, o);
                    v.w += __shfl_xor_sync(0xffffffffu, v.w, o);
                    cc  += __shfl_xor_sync(0xffffffffu, cc, o);
                }
                if (lane == 0) {
                    c_pb[tid >> 5][0] = v.x; c_pb[tid >> 5][1] = v.y;
                    c_pb[tid >> 5][2] = v.z; c_pb[tid >> 5][3] = v.w;
                    c_pc[tid >> 5] = cc;
                }
            }
            __syncthreads();
            if (tid < EMB_D)
                c_w[tid] = c_tw[0][tid] + c_tw[1][tid] + c_tw[2][tid] + c_tw[3][tid];
            if (tid >= 64 && tid < 64 + KTH) {
                const int j = tid - 64;
                c_b[j] = c_pb[0][j] + c_pb[1][j] + c_pb[2][j] + c_pb[3][j];
            }
            if (tid == 128)
                c_c = c_pc[0] + c_pc[1] + c_pc[2] + c_pc[3];
            __syncthreads();

            // Merge corrections into this thread's registers.
            #pragma unroll
            for (int i = 0; i < UNROLL; i++) {
                const long kk = base + (long)i * TPB + tid;
                if (kk < K_CH) {
                    const long s = 4 * kk;
                    merge_elt(prev[i], s,     wlo, whi, blo, bhi, c_w, c_b);
                    merge_elt(B[i].x,  s + 1, wlo, whi, blo, bhi, c_w, c_b);
                    merge_elt(B[i].y,  s + 2, wlo, whi, blo, bhi, c_w, c_b);
                    merge_elt(B[i].z,  s + 3, wlo, whi, blo, bhi, c_w, c_b);
                }
            }

            // Specials (owners).
            const long wo = (wlo > 4) ? wlo : 4;
            const bool is_w_owner = (wo >= rlo && wo < rhi);
            const bool is_b_owner = (blo >= rlo && blo < rhi);
            if (is_w_owner) {
                if (tid == 128) out[0] = (float)c_c * INVB;
                if (tid >= 129 && tid < 132) {
                    const int j = tid - 128;             // 1..3
                    float v = __ldg(emb + (j - 1));
                    if (j >= wlo && j < whi) v += c_w[j - wlo] * INVB; // ctx==0
                    out[j] = v;
                }
            }
            if (is_b_owner && tid == 133) {
                float v = __ldg(bia + B_ELEMS - 1);
                if (ctx == WORDS - 1) v -= c_b[KTH - 1] * INVB;
                out[TOT_ELEMS] = v;
            }

            // Ack; last consumer resets flag + ack (replay-safe).
            __syncthreads();
            if (tid == 0) {
                long wend = whi - 1;
                long bend = bhi - 1;
                if (bend > 4L * K_CH - 1) bend = 4L * K_CH - 1;
                const unsigned int C =
                    (unsigned int)((blk_of(wend) - blk_of(wo) + 1) +
                                   (blk_of(bend) - blk_of(blo) + 1));
                const unsigned int old = atomicAdd(&g_ack, 1u);
                if (old == C - 1u) {
                    g_ack = 0u;
                    __threadfence();
                    g_flag = 0u;
                }
            }
        }
    }

    // ---- the one and only bulk store loop: pure STG.128 ----
    #pragma unroll
    for (int i = 0; i < UNROLL; i++) {
        const long kk = base + (long)i * TPB + tid;
        if (kk < K_CH) {
            __stcs(reinterpret_cast<float4*>(out) + kk,
                   make_float4(prev[i], B[i].x, B[i].y, B[i].z));
        }
    }
}

extern "C" void kernel_launch(void* const* d_in, const int* in_sizes, int n_in,
                              void* d_out, int out_size) {
    const float* in_embed = (const float*)d_in[0];
    const float* in_bias  = (const float*)d_in[1];
    const int*   ctx_id   = (const int*)d_in[2];
    const int*   tgt      = (const int*)d_in[3];
    const int*   lab      = (const int*)d_in[4];
    float* out = (float*)d_out;
    (void)n_in; (void)out_size; (void)in_sizes;

    const long nchunks = K_CH - 1;                       // chunks 1..K_CH-1
    const int  blocks  = (int)((nchunks + CPB - 1) / CPB);
    prank_main_kernel<<<blocks, TPB>>>(in_embed, in_bias, ctx_id, tgt, lab, out);
}

// round 16
// speedup vs baseline: 1.0943x; 1.0233x over previous
#include <cuda_runtime.h>
#include <cstddef>

#define WORDS   1000000
#define EMB_D   64
#define KTH     4
#define BATCH   8192

#define E_ELEMS   (WORDS * EMB_D)                // 64,000,000 (fits int)
#define B_ELEMS   (WORDS * KTH)                  // 4,000,000
#define TOT_ELEMS (E_ELEMS + B_ELEMS)            // 68,000,000
#define K_CH      (TOT_ELEMS / 4)                // 17,000,000 chunks
#define E_CH      (E_ELEMS / 4)                  // 16,000,000
#define RB        128
#define INVB      (1.0f / (float)BATCH)

#define TPB     256
#define UNROLL  4
#define CPB     (TPB * UNROLL)                   // 1024 chunks per block

// Per-block partials (fully overwritten each launch -> graph-replay safe).
__device__ float g_pw[RB][EMB_D];
__device__ float g_pb[RB][KTH];
__device__ int   g_pc[RB];
// Sync state; every word returns to 0 each launch -> graph-replay safe.
__device__ unsigned int g_ticket;
__device__ unsigned int g_flag;
__device__ unsigned int g_ack;

// ---------------------------------------------------------------------------
// Helpers (int32 indices throughout)
// ---------------------------------------------------------------------------
__device__ __forceinline__ float load_src(int s,
                                          const float* __restrict__ emb,
                                          const float* __restrict__ bia) {
    return (s < E_ELEMS) ? __ldg(emb + s) : __ldg(bia + (s - E_ELEMS));
}

__device__ __forceinline__ float4 load_chunk_cs(int k,
                                                const float* __restrict__ emb,
                                                const float* __restrict__ bia) {
    const float4* p = (k < E_CH)
        ? (reinterpret_cast<const float4*>(emb) + k)
        : (reinterpret_cast<const float4*>(bia) + (k - E_CH));
    return __ldcs(p);
}

// ---------------------------------------------------------------------------
// Reduce body (blocks 0..RB-1)
// ---------------------------------------------------------------------------
__device__ void reduce_body(const float* __restrict__ embed,
                            const float* __restrict__ bias,
                            const int*   __restrict__ ctx_id,
                            const int*   __restrict__ tgt,
                            const int*   __restrict__ lab) {
    __shared__ float s_ctx[EMB_D];
    __shared__ float s_bias[KTH];
    __shared__ float s_w[8][EMB_D];
    __shared__ float s_b[8][KTH];
    __shared__ int   s_c[8];

    const int tid = threadIdx.x;
    const int ctx = __ldg(ctx_id);
    if (tid < EMB_D) s_ctx[tid]  = __ldg(embed + (size_t)ctx * EMB_D + tid);
    if (tid < KTH)   s_bias[tid] = __ldg(bias  + (size_t)ctx * KTH + tid);
    __syncthreads();

    const int warp  = tid >> 5;
    const int lane  = tid & 31;
    const int gwarp = blockIdx.x * 8 + warp;
    const int twarps = RB * 8;

    const float2 c2 = reinterpret_cast<const float2*>(s_ctx)[lane];

    float wx = 0.0f, wy = 0.0f;
    float b0 = 0.0f, b1 = 0.0f, b2 = 0.0f, b3 = 0.0f;
    int corr = 0;

    for (int b = gwarp; b < BATCH; b += twarps) {
        const int t = __ldg(tgt + b);
        const float2 e2 =
            reinterpret_cast<const float2*>(embed + (size_t)t * EMB_D)[lane];
        float p = e2.x * c2.x + e2.y * c2.y;
        #pragma unroll
        for (int o = 16; o; o >>= 1) p += __shfl_xor_sync(0xffffffffu, p, o);
        const float dot = p;

        const int   L    = __ldg(lab + b);
        const float labf = (float)L;

        float taurow = 0.0f;
        int   plabel = KTH + 1;
        float tj[KTH];
        #pragma unroll
        for (int j = KTH - 1; j >= 0; j--) {
            const float db = dot - s_bias[j];
            if (db <= 0.0f) plabel = j + 1;
            const float yt  = (j < L) ? 1.0f : -1.0f;
            const float tau = (db * yt > 0.0f) ? 0.0f : labf;
            tj[j] = tau;
            taurow += tau;
        }
        if (lane == 0) {
            b0 += tj[0]; b1 += tj[1]; b2 += tj[2]; b3 += tj[3];
            if (plabel == L) corr++;
        }
        wx += taurow * e2.x;
        wy += taurow * e2.y;
    }

    s_w[warp][2 * lane]     = wx;
    s_w[warp][2 * lane + 1] = wy;
    if (lane == 0) {
        s_b[warp][0] = b0; s_b[warp][1] = b1; s_b[warp][2] = b2; s_b[warp][3] = b3;
        s_c[warp] = corr;
    }
    __syncthreads();

    if (tid < EMB_D) {
        float s = 0.0f;
        #pragma unroll
        for (int w = 0; w < 8; w++) s += s_w[w][tid];
        g_pw[blockIdx.x][tid] = s;
    }
    if (tid < KTH) {
        float s = 0.0f;
        #pragma unroll
        for (int w = 0; w < 8; w++) s += s_b[w][tid];
        g_pb[blockIdx.x][tid] = s;
    }
    if (tid == 0) {
        int s = 0;
        #pragma unroll
        for (int w = 0; w < 8; w++) s += s_c[w];
        g_pc[blockIdx.x] = s;
    }
}

// Merge the context-row correction into one register (consumer blocks only).
__device__ __forceinline__ void merge_elt(float& r, int idx,
                                          int wlo, int whi, int blo, int bhi,
                                          const float* s_w, const float* s_b) {
    if (idx >= wlo && idx < whi) r += s_w[idx - wlo] * INVB;
    if (idx >= blo && idx < bhi) r -= s_b[idx - blo] * INVB;
}

__device__ __forceinline__ int blk_of(int idx) { return (idx - 4) >> 12; }

// ---------------------------------------------------------------------------
// Single fused kernel. One float4 store loop carries ALL bulk output traffic.
// ---------------------------------------------------------------------------
__global__ void __launch_bounds__(TPB, 6)
prank_main_kernel(const float* __restrict__ emb,
                  const float* __restrict__ bia,
                  const int*   __restrict__ ctx_id,
                  const int*   __restrict__ tgt,
                  const int*   __restrict__ lab,
                  float* __restrict__ out) {
    __shared__ float c_tw[4][EMB_D];
    __shared__ float c_w[EMB_D];
    __shared__ float c_pb[4][KTH];
    __shared__ int   c_pc[4];
    __shared__ float c_b[KTH];
    __shared__ int   c_c;

    const int tid  = threadIdx.x;
    const int lane = tid & 31;

    if (blockIdx.x < RB) {
        reduce_body(emb, bia, ctx_id, tgt, lab);
        __threadfence();                     // publish partials (RB blocks only)
        __syncthreads();
        if (tid == 0) {
            const unsigned int old = atomicAdd(&g_ticket, 1u);
            if (old == RB - 1u) {
                g_ticket = 0;                // replay-safe reset
                atomicExch(&g_flag, 1u);     // release
            }
        }
    }

    const int base = blockIdx.x * CPB + 1;

    // ---- load phase ----
    float4 B[UNROLL];
    float  prev[UNROLL];

    #pragma unroll
    for (int i = 0; i < UNROLL; i++) {
        int kk = base + i * TPB + tid;
        if (kk >= K_CH) kk = K_CH - 1;       // clamp keeps warp converged
        B[i] = load_chunk_cs(kk, emb, bia);
    }

    #pragma unroll
    for (int i = 0; i < UNROLL; i++) {
        prev[i] = __shfl_up_sync(0xffffffffu, B[i].w, 1);
        if (lane == 0) {
            int kk = base + i * TPB + tid;
            if (kk >= K_CH) kk = K_CH - 1;
            prev[i] = load_src(4 * kk - 1, emb, bia);
        }
    }

    // ---- consumer branch: <=3 blocks chip-wide merge corrections in-reg ----
    {
        const int ctx = __ldg(ctx_id);
        const int wlo = 1 + ctx * EMB_D,       whi = wlo + EMB_D;
        const int blo = 1 + E_ELEMS + ctx * KTH, bhi = blo + KTH;
        const int rlo = 4 * base;
        int rhi = rlo + 4 * CPB;
        if (rhi > 4 * K_CH) rhi = 4 * K_CH;

        const bool ov = (rlo < whi && rhi > wlo) || (rlo < bhi && rhi > blo);

        if (ov) {
            if (tid == 0) {
                while (atomicAdd(&g_flag, 0u) == 0u) { __nanosleep(64); }
            }
            __syncthreads();
            __threadfence();                 // acquire partials

            {
                const int g = tid >> 6;
                const int c = tid & 63;
                float acc = 0.0f;
                #pragma unroll
                for (int i = 0; i < RB / 4; i++)
                    acc += g_pw[g + 4 * i][c];
                c_tw[g][c] = acc;
            }
            if (tid < 128) {
                float4 v = reinterpret_cast<const float4*>(g_pb)[tid];
                int cc = g_pc[tid];
                #pragma unroll
                for (int o = 16; o; o >>= 1) {
                    v.x += __shfl_xor_sync(0xffffffffu, v.x, o);
                    v.y += __shfl_xor_sync(0xffffffffu, v.y, o);
                    v.z += __shfl_xor_sync(0xffffffffu, v.z, o);
                    v.w += __shfl_xor_sync(0xffffffffu, v.w, o);
                    cc  += __shfl_xor_sync(0xffffffffu, cc, o);
                }
                if (lane == 0) {
                    c_pb[tid >> 5][0] = v.x; c_pb[tid >> 5][1] = v.y;
                    c_pb[tid >> 5][2] = v.z; c_pb[tid >> 5][3] = v.w;
                    c_pc[tid >> 5] = cc;
                }
            }
            __syncthreads();
            if (tid < EMB_D)
                c_w[tid] = c_tw[0][tid] + c_tw[1][tid] + c_tw[2][tid] + c_tw[3][tid];
            if (tid >= 64 && tid < 64 + KTH) {
                const int j = tid - 64;
                c_b[j] = c_pb[0][j] + c_pb[1][j] + c_pb[2][j] + c_pb[3][j];
            }
            if (tid == 128)
                c_c = c_pc[0] + c_pc[1] + c_pc[2] + c_pc[3];
            __syncthreads();

            #pragma unroll
            for (int i = 0; i < UNROLL; i++) {
                const int kk = base + i * TPB + tid;
                if (kk < K_CH) {
                    const int s = 4 * kk;
                    merge_elt(prev[i], s,     wlo, whi, blo, bhi, c_w, c_b);
                    merge_elt(B[i].x,  s + 1, wlo, whi, blo, bhi, c_w, c_b);
                    merge_elt(B[i].y,  s + 2, wlo, whi, blo, bhi, c_w, c_b);
                    merge_elt(B[i].z,  s + 3, wlo, whi, blo, bhi, c_w, c_b);
                }
            }

            // Specials (owners).
            const int wo = (wlo > 4) ? wlo : 4;
            const bool is_w_owner = (wo >= rlo && wo < rhi);
            const bool is_b_owner = (blo >= rlo && blo < rhi);
            if (is_w_owner) {
                if (tid == 128) out[0] = (float)c_c * INVB;
                if (tid >= 129 && tid < 132) {
                    const int j = tid - 128;             // 1..3
                    float v = __ldg(emb + (j - 1));
                    if (j >= wlo && j < whi) v += c_w[j - wlo] * INVB; // ctx==0
                    out[j] = v;
                }
            }
            if (is_b_owner && tid == 133) {
                float v = __ldg(bia + B_ELEMS - 1);
                if (ctx == WORDS - 1) v -= c_b[KTH - 1] * INVB;
                out[TOT_ELEMS] = v;
            }

            // Ack; last consumer resets flag + ack (replay-safe).
            __syncthreads();
            if (tid == 0) {
                int wend = whi - 1;
                int bend = bhi - 1;
                if (bend > 4 * K_CH - 1) bend = 4 * K_CH - 1;
                const unsigned int C =
                    (unsigned int)((blk_of(wend) - blk_of(wo) + 1) +
                                   (blk_of(bend) - blk_of(blo) + 1));
                const unsigned int old = atomicAdd(&g_ack, 1u);
                if (old == C - 1u) {
                    g_ack = 0u;
                    __threadfence();
                    g_flag = 0u;
                }
            }
        }
    }

    // ---- the one and only bulk store loop: pure STG.128 ----
    #pragma unroll
    for (int i = 0; i < UNROLL; i++) {
        const int kk = base + i * TPB + tid;
        if (kk < K_CH) {
            __stcs(reinterpret_cast<float4*>(out) + kk,
                   make_float4(prev[i], B[i].x, B[i].y, B[i].z));
        }
    }
}

extern "C" void kernel_launch(void* const* d_in, const int* in_sizes, int n_in,
                              void* d_out, int out_size) {
    const float* in_embed = (const float*)d_in[0];
    const float* in_bias  = (const float*)d_in[1];
    const int*   ctx_id   = (const int*)d_in[2];
    const int*   tgt      = (const int*)d_in[3];
    const int*   lab      = (const int*)d_in[4];
    float* out = (float*)d_out;
    (void)n_in; (void)out_size; (void)in_sizes;

    const int nchunks = K_CH - 1;                        // chunks 1..K_CH-1
    const int blocks  = (nchunks + CPB - 1) / CPB;
    prank_main_kernel<<<blocks, TPB>>>(in_embed, in_bias, ctx_id, tgt, lab, out);
}